// round 1
// baseline (speedup 1.0000x reference)
#include <cuda_runtime.h>
#include <cstdint>

// Problem constants (match reference)
#define Lc 4
#define Gc 20000
#define Cc 128
#define Ec 320000
#define KDc 16
#define NROWS (Lc*Gc)          // 80000 state rows of length 128
#define LN_EPS 1e-5f

// ---------------- device scratch (static: no allocation APIs) --------------
__device__ float g_bufA[(size_t)Lc*Gc*Cc];   // xr1
__device__ float g_bufB[(size_t)Lc*Gc*Cc];   // xr2
__device__ float g_weights[NROWS];
__device__ int   g_rowptr[Gc+1];
__device__ int   g_cnt[Gc];
__device__ int   g_fill[Gc];
__device__ int   g_ecol[Ec];
__device__ float g_eval[Ec];
__device__ float g_WkT[KDc*Cc];              // [d][j]
__device__ float g_WqT[KDc*Cc];
__device__ float g_WvT[Cc*Cc];               // [c][j]

// ---------------- packed fp32x2 FMA helpers --------------------------------
__device__ __forceinline__ void fma2(unsigned long long& acc,
                                     unsigned long long a,
                                     unsigned long long b) {
    asm("fma.rn.f32x2 %0, %1, %2, %3;" : "=l"(acc) : "l"(a), "l"(b), "l"(acc));
}
__device__ __forceinline__ float unpack_sum(unsigned long long v) {
    float lo, hi;
    asm("mov.b64 {%0,%1}, %2;" : "=f"(lo), "=f"(hi) : "l"(v));
    return lo + hi;
}

// ---------------- CSR build -------------------------------------------------
__global__ void zero_cnt_kernel() {
    int i = blockIdx.x * blockDim.x + threadIdx.x;
    if (i < Gc) g_cnt[i] = 0;
}

__global__ void count_kernel(const int* __restrict__ erow, int E) {
    int i = blockIdx.x * blockDim.x + threadIdx.x;
    if (i < E) atomicAdd(&g_cnt[erow[i]], 1);
}

__global__ void scan_kernel() {
    __shared__ int sh[1024];
    __shared__ int carry_s;
    int tid = threadIdx.x;
    if (tid == 0) carry_s = 0;
    __syncthreads();
    for (int base = 0; base < Gc; base += 1024) {
        int idx = base + tid;
        int v = (idx < Gc) ? g_cnt[idx] : 0;
        sh[tid] = v;
        __syncthreads();
        // inclusive scan (Hillis-Steele)
        for (int o = 1; o < 1024; o <<= 1) {
            int t = (tid >= o) ? sh[tid - o] : 0;
            __syncthreads();
            sh[tid] += t;
            __syncthreads();
        }
        int carry = carry_s;
        if (idx < Gc) {
            int excl = carry + sh[tid] - v;
            g_rowptr[idx] = excl;
            g_fill[idx]   = excl;
        }
        __syncthreads();
        if (tid == 1023) carry_s = carry + sh[1023];
        __syncthreads();
    }
    if (tid == 0) g_rowptr[Gc] = carry_s;
}

__global__ void scatter_kernel(const int* __restrict__ erow,
                               const int* __restrict__ ecol,
                               const float* __restrict__ ev, int E) {
    int i = blockIdx.x * blockDim.x + threadIdx.x;
    if (i < E) {
        int r = erow[i];
        int p = atomicAdd(&g_fill[r], 1);
        g_ecol[p] = ecol[i];
        g_eval[p] = ev[i];
    }
}

// ---------------- weight-matrix transposes ----------------------------------
__global__ void transpose_kernel(const float* __restrict__ Wk,
                                 const float* __restrict__ Wq,
                                 const float* __restrict__ Wv) {
    int i = blockIdx.x * blockDim.x + threadIdx.x;   // up to 16384
    if (i < Cc * KDc) {
        int j = i >> 4, d = i & 15;                  // Wk[j][d]
        g_WkT[d * Cc + j] = Wk[i];
        g_WqT[d * Cc + j] = Wq[i];
    }
    if (i < Cc * Cc) {
        int j = i >> 7, c = i & 127;                 // Wv[j][c]
        g_WvT[c * Cc + j] = Wv[i];
    }
}

// ---------------- weights: w[R] (+)= mean_d( (x@Wk)_d * (x@Wq)_d ) ----------
// 256 threads = 16 rows x 16 d. Grid = NROWS/16 = 5000.
__global__ void weights_kernel(const float* __restrict__ x, int sel, int accum) {
    int tid  = threadIdx.x;
    int rloc = tid >> 4;
    int d    = tid & 15;
    int R    = blockIdx.x * 16 + rloc;
    if (R >= NROWS) return;

    const float* state = (sel == 0) ? x : (sel == 1 ? g_bufA : g_bufB);
    const unsigned long long* xp =
        reinterpret_cast<const unsigned long long*>(state + (size_t)R * Cc);
    const unsigned long long* kp =
        reinterpret_cast<const unsigned long long*>(g_WkT + d * Cc);
    const unsigned long long* qp =
        reinterpret_cast<const unsigned long long*>(g_WqT + d * Cc);

    unsigned long long k2 = 0ull, q2 = 0ull;
    #pragma unroll
    for (int j = 0; j < Cc / 2; j++) {
        unsigned long long xv = xp[j];
        fma2(k2, xv, kp[j]);
        fma2(q2, xv, qp[j]);
    }
    float p = unpack_sum(k2) * unpack_sum(q2);
    #pragma unroll
    for (int o = 8; o; o >>= 1) p += __shfl_xor_sync(0xffffffffu, p, o);
    if (d == 0) {
        float val = p * (1.0f / KDc);
        g_weights[R] = accum ? (g_weights[R] + val) : val;
    }
}

// ---------------- SPMM: dst[l,g,:] = 0.5 * sum_e val_e * src[l,col_e,:] ----
// Block per output g. 128 threads: l = t>>5 (0..3), 4 cols per thread.
__global__ void spmm_kernel(const float* __restrict__ x, int iter) {
    const float* src = (iter == 0) ? x : g_bufA;
    float* dst       = (iter == 0) ? g_bufA : g_bufB;

    int g = blockIdx.x;
    int t = threadIdx.x;               // 128
    int l  = t >> 5;
    int c4 = (t & 31) * 4;

    int s = g_rowptr[g], e = g_rowptr[g + 1];
    __shared__ int   scol[128];
    __shared__ float sval[128];

    float4 acc = make_float4(0.f, 0.f, 0.f, 0.f);
    const float* srcb = src + (size_t)l * Gc * Cc + c4;

    for (int base = s; base < e; base += 128) {
        int n = min(128, e - base);
        if (t < n) {
            scol[t] = g_ecol[base + t];
            sval[t] = g_eval[base + t];
        }
        __syncthreads();
        #pragma unroll 4
        for (int i = 0; i < n; i++) {
            float v = sval[i];
            int  cc = scol[i];
            float4 sv = *reinterpret_cast<const float4*>(srcb + (size_t)cc * Cc);
            acc.x += v * sv.x; acc.y += v * sv.y;
            acc.z += v * sv.z; acc.w += v * sv.w;
        }
        __syncthreads();
    }
    float4 o = make_float4(acc.x * 0.5f, acc.y * 0.5f, acc.z * 0.5f, acc.w * 0.5f);
    *reinterpret_cast<float4*>(dst + ((size_t)l * Gc + g) * Cc + c4) = o;
}

// ---------------- final: values = (x+A+B)@Wv, v = values*w, LayerNorm -------
// Block per row R (80000 blocks), 128 threads (one per output column).
__global__ void final_kernel(const float* __restrict__ x,
                             const float* __restrict__ gamma,
                             const float* __restrict__ beta,
                             float* __restrict__ out) {
    int R = blockIdx.x;
    int c = threadIdx.x;
    size_t off = (size_t)R * Cc;

    __shared__ __align__(16) float s[Cc];
    s[c] = x[off + c] + g_bufA[off + c] + g_bufB[off + c];
    __syncthreads();

    const ulonglong2* sp = reinterpret_cast<const ulonglong2*>(s);
    const ulonglong2* wp =
        reinterpret_cast<const ulonglong2*>(g_WvT + (size_t)c * Cc);
    unsigned long long acc2 = 0ull;
    #pragma unroll
    for (int j = 0; j < Cc / 4; j++) {
        ulonglong2 a = sp[j];
        ulonglong2 b = wp[j];
        fma2(acc2, a.x, b.x);
        fma2(acc2, a.y, b.y);
    }
    float v = unpack_sum(acc2) * g_weights[R];

    // LayerNorm over 128 lanes (4 warps)
    int wid = c >> 5, lane = c & 31;
    __shared__ float red[4];
    __shared__ float mu_s, rstd_s;

    float t = v;
    #pragma unroll
    for (int o = 16; o; o >>= 1) t += __shfl_xor_sync(0xffffffffu, t, o);
    if (lane == 0) red[wid] = t;
    __syncthreads();
    if (c == 0) mu_s = (red[0] + red[1] + red[2] + red[3]) * (1.0f / Cc);
    __syncthreads();
    float mu = mu_s;
    float d = v - mu;
    t = d * d;
    #pragma unroll
    for (int o = 16; o; o >>= 1) t += __shfl_xor_sync(0xffffffffu, t, o);
    if (lane == 0) red[wid] = t;
    __syncthreads();
    if (c == 0) {
        float var = (red[0] + red[1] + red[2] + red[3]) * (1.0f / Cc);
        rstd_s = rsqrtf(var + LN_EPS);
    }
    __syncthreads();
    out[off + c] = d * rstd_s * gamma[c] + beta[c];
}

// ---------------- launch ----------------------------------------------------
extern "C" void kernel_launch(void* const* d_in, const int* in_sizes, int n_in,
                              void* d_out, int out_size) {
    const float* x     = (const float*)d_in[0];
    const int*   erow  = (const int*)  d_in[1];
    const int*   ecol  = (const int*)  d_in[2];
    const float* evals = (const float*)d_in[3];
    const float* Wk    = (const float*)d_in[4];
    const float* Wq    = (const float*)d_in[5];
    const float* Wv    = (const float*)d_in[6];
    const float* gamma = (const float*)d_in[7];
    const float* beta  = (const float*)d_in[8];
    float* out = (float*)d_out;
    int E = in_sizes[1];
    if (E > Ec) E = Ec;

    // CSR build
    zero_cnt_kernel<<<(Gc + 255) / 256, 256>>>();
    count_kernel<<<(E + 255) / 256, 256>>>(erow, E);
    scan_kernel<<<1, 1024>>>();
    scatter_kernel<<<(E + 255) / 256, 256>>>(erow, ecol, evals, E);

    // weight transposes
    transpose_kernel<<<64, 256>>>(Wk, Wq, Wv);

    // weights from x; two SPMM iterations, each adding weight contribution
    weights_kernel<<<NROWS / 16, 256>>>(x, 0, 0);
    spmm_kernel<<<Gc, 128>>>(x, 0);
    weights_kernel<<<NROWS / 16, 256>>>(x, 1, 1);
    spmm_kernel<<<Gc, 128>>>(x, 1);
    weights_kernel<<<NROWS / 16, 256>>>(x, 2, 1);

    // fused GEMM + scale + LayerNorm
    final_kernel<<<NROWS, 128>>>(x, gamma, beta, out);
}

// round 2
// speedup vs baseline: 1.0007x; 1.0007x over previous
#include <cuda_runtime.h>
#include <cstdint>

// Problem constants (match reference)
#define Lc 4
#define Gc 20000
#define Cc 128
#define Ec 320000
#define KDc 16
#define NROWS (Lc*Gc)          // 80000 state rows of length 128
#define LN_EPS 1e-5f

// ---------------- device scratch (static: no allocation APIs) --------------
__device__ float g_bufA[(size_t)Lc*Gc*Cc];   // xr1
__device__ float g_bufB[(size_t)Lc*Gc*Cc];   // xr2
__device__ float g_weights[NROWS];
__device__ int   g_rowptr[Gc+1];
__device__ int   g_cnt[Gc];
__device__ int   g_fill[Gc];
__device__ int   g_ecol[Ec];
__device__ float g_eval[Ec];
__device__ float g_WkT[KDc*Cc];              // [d][j]
__device__ float g_WqT[KDc*Cc];
__device__ float g_WvT[Cc*Cc];               // [c][j]

// ---------------- packed fp32x2 FMA helpers --------------------------------
__device__ __forceinline__ void fma2(unsigned long long& acc,
                                     unsigned long long a,
                                     unsigned long long b) {
    asm("fma.rn.f32x2 %0, %1, %2, %3;" : "=l"(acc) : "l"(a), "l"(b), "l"(acc));
}
__device__ __forceinline__ float unpack_sum(unsigned long long v) {
    float lo, hi;
    asm("mov.b64 {%0,%1}, %2;" : "=f"(lo), "=f"(hi) : "l"(v));
    return lo + hi;
}

// ---------------- CSR build -------------------------------------------------
__global__ void zero_cnt_kernel() {
    int i = blockIdx.x * blockDim.x + threadIdx.x;
    if (i < Gc) g_cnt[i] = 0;
}

__global__ void count_kernel(const int* __restrict__ erow, int E) {
    int i = blockIdx.x * blockDim.x + threadIdx.x;
    if (i < E) atomicAdd(&g_cnt[erow[i]], 1);
}

__global__ void scan_kernel() {
    __shared__ int sh[1024];
    __shared__ int carry_s;
    int tid = threadIdx.x;
    if (tid == 0) carry_s = 0;
    __syncthreads();
    for (int base = 0; base < Gc; base += 1024) {
        int idx = base + tid;
        int v = (idx < Gc) ? g_cnt[idx] : 0;
        sh[tid] = v;
        __syncthreads();
        // inclusive scan (Hillis-Steele)
        for (int o = 1; o < 1024; o <<= 1) {
            int t = (tid >= o) ? sh[tid - o] : 0;
            __syncthreads();
            sh[tid] += t;
            __syncthreads();
        }
        int carry = carry_s;
        if (idx < Gc) {
            int excl = carry + sh[tid] - v;
            g_rowptr[idx] = excl;
            g_fill[idx]   = excl;
        }
        __syncthreads();
        if (tid == 1023) carry_s = carry + sh[1023];
        __syncthreads();
    }
    if (tid == 0) g_rowptr[Gc] = carry_s;
}

__global__ void scatter_kernel(const int* __restrict__ erow,
                               const int* __restrict__ ecol,
                               const float* __restrict__ ev, int E) {
    int i = blockIdx.x * blockDim.x + threadIdx.x;
    if (i < E) {
        int r = erow[i];
        int p = atomicAdd(&g_fill[r], 1);
        g_ecol[p] = ecol[i];
        g_eval[p] = ev[i];
    }
}

// ---------------- weight-matrix transposes ----------------------------------
__global__ void transpose_kernel(const float* __restrict__ Wk,
                                 const float* __restrict__ Wq,
                                 const float* __restrict__ Wv) {
    int i = blockIdx.x * blockDim.x + threadIdx.x;   // up to 16384
    if (i < Cc * KDc) {
        int j = i >> 4, d = i & 15;                  // Wk[j][d]
        g_WkT[d * Cc + j] = Wk[i];
        g_WqT[d * Cc + j] = Wq[i];
    }
    if (i < Cc * Cc) {
        int j = i >> 7, c = i & 127;                 // Wv[j][c]
        g_WvT[c * Cc + j] = Wv[i];
    }
}

// ---------------- weights: w[R] (+)= mean_d( (x@Wk)_d * (x@Wq)_d ) ----------
// 256 threads = 16 rows x 16 d. Grid = NROWS/16 = 5000.
__global__ void weights_kernel(const float* __restrict__ x, int sel, int accum) {
    int tid  = threadIdx.x;
    int rloc = tid >> 4;
    int d    = tid & 15;
    int R    = blockIdx.x * 16 + rloc;
    if (R >= NROWS) return;

    const float* state = (sel == 0) ? x : (sel == 1 ? g_bufA : g_bufB);
    const unsigned long long* xp =
        reinterpret_cast<const unsigned long long*>(state + (size_t)R * Cc);
    const unsigned long long* kp =
        reinterpret_cast<const unsigned long long*>(g_WkT + d * Cc);
    const unsigned long long* qp =
        reinterpret_cast<const unsigned long long*>(g_WqT + d * Cc);

    unsigned long long k2 = 0ull, q2 = 0ull;
    #pragma unroll
    for (int j = 0; j < Cc / 2; j++) {
        unsigned long long xv = xp[j];
        fma2(k2, xv, kp[j]);
        fma2(q2, xv, qp[j]);
    }
    float p = unpack_sum(k2) * unpack_sum(q2);
    #pragma unroll
    for (int o = 8; o; o >>= 1) p += __shfl_xor_sync(0xffffffffu, p, o);
    if (d == 0) {
        float val = p * (1.0f / KDc);
        g_weights[R] = accum ? (g_weights[R] + val) : val;
    }
}

// ---------------- SPMM: dst[l,g,:] = 0.5 * sum_e val_e * src[l,col_e,:] ----
// Block per output g. 128 threads: l = t>>5 (0..3), 4 cols per thread.
__global__ void spmm_kernel(const float* __restrict__ x, int iter) {
    const float* src = (iter == 0) ? x : g_bufA;
    float* dst       = (iter == 0) ? g_bufA : g_bufB;

    int g = blockIdx.x;
    int t = threadIdx.x;               // 128
    int l  = t >> 5;
    int c4 = (t & 31) * 4;

    int s = g_rowptr[g], e = g_rowptr[g + 1];
    __shared__ int   scol[128];
    __shared__ float sval[128];

    float4 acc = make_float4(0.f, 0.f, 0.f, 0.f);
    const float* srcb = src + (size_t)l * Gc * Cc + c4;

    for (int base = s; base < e; base += 128) {
        int n = min(128, e - base);
        if (t < n) {
            scol[t] = g_ecol[base + t];
            sval[t] = g_eval[base + t];
        }
        __syncthreads();
        #pragma unroll 4
        for (int i = 0; i < n; i++) {
            float v = sval[i];
            int  cc = scol[i];
            float4 sv = *reinterpret_cast<const float4*>(srcb + (size_t)cc * Cc);
            acc.x += v * sv.x; acc.y += v * sv.y;
            acc.z += v * sv.z; acc.w += v * sv.w;
        }
        __syncthreads();
    }
    float4 o = make_float4(acc.x * 0.5f, acc.y * 0.5f, acc.z * 0.5f, acc.w * 0.5f);
    *reinterpret_cast<float4*>(dst + ((size_t)l * Gc + g) * Cc + c4) = o;
}

// ---------------- final: values = (x+A+B)@Wv, v = values*w, LayerNorm -------
// Block per row R (80000 blocks), 128 threads (one per output column).
__global__ void final_kernel(const float* __restrict__ x,
                             const float* __restrict__ gamma,
                             const float* __restrict__ beta,
                             float* __restrict__ out) {
    int R = blockIdx.x;
    int c = threadIdx.x;
    size_t off = (size_t)R * Cc;

    __shared__ __align__(16) float s[Cc];
    s[c] = x[off + c] + g_bufA[off + c] + g_bufB[off + c];
    __syncthreads();

    const ulonglong2* sp = reinterpret_cast<const ulonglong2*>(s);
    const ulonglong2* wp =
        reinterpret_cast<const ulonglong2*>(g_WvT + (size_t)c * Cc);
    unsigned long long acc2 = 0ull;
    #pragma unroll
    for (int j = 0; j < Cc / 4; j++) {
        ulonglong2 a = sp[j];
        ulonglong2 b = wp[j];
        fma2(acc2, a.x, b.x);
        fma2(acc2, a.y, b.y);
    }
    float v = unpack_sum(acc2) * g_weights[R];

    // LayerNorm over 128 lanes (4 warps)
    int wid = c >> 5, lane = c & 31;
    __shared__ float red[4];
    __shared__ float mu_s, rstd_s;

    float t = v;
    #pragma unroll
    for (int o = 16; o; o >>= 1) t += __shfl_xor_sync(0xffffffffu, t, o);
    if (lane == 0) red[wid] = t;
    __syncthreads();
    if (c == 0) mu_s = (red[0] + red[1] + red[2] + red[3]) * (1.0f / Cc);
    __syncthreads();
    float mu = mu_s;
    float d = v - mu;
    t = d * d;
    #pragma unroll
    for (int o = 16; o; o >>= 1) t += __shfl_xor_sync(0xffffffffu, t, o);
    if (lane == 0) red[wid] = t;
    __syncthreads();
    if (c == 0) {
        float var = (red[0] + red[1] + red[2] + red[3]) * (1.0f / Cc);
        rstd_s = rsqrtf(var + LN_EPS);
    }
    __syncthreads();
    out[off + c] = d * rstd_s * gamma[c] + beta[c];
}

// ---------------- launch ----------------------------------------------------
extern "C" void kernel_launch(void* const* d_in, const int* in_sizes, int n_in,
                              void* d_out, int out_size) {
    const float* x     = (const float*)d_in[0];
    const int*   erow  = (const int*)  d_in[1];
    const int*   ecol  = (const int*)  d_in[2];
    const float* evals = (const float*)d_in[3];
    const float* Wk    = (const float*)d_in[4];
    const float* Wq    = (const float*)d_in[5];
    const float* Wv    = (const float*)d_in[6];
    const float* gamma = (const float*)d_in[7];
    const float* beta  = (const float*)d_in[8];
    float* out = (float*)d_out;
    int E = in_sizes[1];
    if (E > Ec) E = Ec;

    // CSR build
    zero_cnt_kernel<<<(Gc + 255) / 256, 256>>>();
    count_kernel<<<(E + 255) / 256, 256>>>(erow, E);
    scan_kernel<<<1, 1024>>>();
    scatter_kernel<<<(E + 255) / 256, 256>>>(erow, ecol, evals, E);

    // weight transposes
    transpose_kernel<<<64, 256>>>(Wk, Wq, Wv);

    // weights from x; two SPMM iterations, each adding weight contribution
    weights_kernel<<<NROWS / 16, 256>>>(x, 0, 0);
    spmm_kernel<<<Gc, 128>>>(x, 0);
    weights_kernel<<<NROWS / 16, 256>>>(x, 1, 1);
    spmm_kernel<<<Gc, 128>>>(x, 1);
    weights_kernel<<<NROWS / 16, 256>>>(x, 2, 1);

    // fused GEMM + scale + LayerNorm
    final_kernel<<<NROWS, 128>>>(x, gamma, beta, out);
}

// round 3
// speedup vs baseline: 8.5774x; 8.5711x over previous
#include <cuda_runtime.h>
#include <cstdint>

// Problem constants (match reference)
#define Lc 4
#define Gc 20000
#define Cc 128
#define Ec 320000
#define KDc 16
#define NROWS (Lc*Gc)          // 80000 state rows of length 128
#define LN_EPS 1e-5f

// ---------------- device scratch (static: no allocation APIs) --------------
__device__ float g_bufA[(size_t)Lc*Gc*Cc];   // xr1
__device__ float g_bufB[(size_t)Lc*Gc*Cc];   // xr2
__device__ float g_weights[NROWS];
__device__ int   g_rowptr[Gc+1];
__device__ int   g_cnt[Gc];
__device__ int   g_fill[Gc];
__device__ int   g_ecol[Ec];
__device__ float g_eval[Ec];
__device__ float g_Wkq[Cc*32];               // [j][0:16]=Wk[j][:], [j][16:32]=Wq[j][:]

// ---------------- packed fp32x2 FMA helpers --------------------------------
__device__ __forceinline__ void fma2(unsigned long long& acc,
                                     unsigned long long a,
                                     unsigned long long b) {
    asm("fma.rn.f32x2 %0, %1, %2, %3;" : "=l"(acc) : "l"(a), "l"(b), "l"(acc));
}
__device__ __forceinline__ unsigned long long pack2(float lo, float hi) {
    unsigned long long v;
    asm("mov.b64 %0, {%1,%2};" : "=l"(v) : "f"(lo), "f"(hi));
    return v;
}
__device__ __forceinline__ void unpack2(unsigned long long v, float& lo, float& hi) {
    asm("mov.b64 {%0,%1}, %2;" : "=f"(lo), "=f"(hi) : "l"(v));
}

// ---------------- CSR build -------------------------------------------------
__global__ void zero_cnt_kernel() {
    int i = blockIdx.x * blockDim.x + threadIdx.x;
    if (i < Gc) g_cnt[i] = 0;
}

__global__ void count_kernel(const int* __restrict__ erow, int E) {
    int i = blockIdx.x * blockDim.x + threadIdx.x;
    if (i < E) atomicAdd(&g_cnt[erow[i]], 1);
}

__global__ void scan_kernel() {
    __shared__ int sh[1024];
    __shared__ int carry_s;
    int tid = threadIdx.x;
    if (tid == 0) carry_s = 0;
    __syncthreads();
    for (int base = 0; base < Gc; base += 1024) {
        int idx = base + tid;
        int v = (idx < Gc) ? g_cnt[idx] : 0;
        sh[tid] = v;
        __syncthreads();
        for (int o = 1; o < 1024; o <<= 1) {
            int t = (tid >= o) ? sh[tid - o] : 0;
            __syncthreads();
            sh[tid] += t;
            __syncthreads();
        }
        int carry = carry_s;
        if (idx < Gc) {
            int excl = carry + sh[tid] - v;
            g_rowptr[idx] = excl;
            g_fill[idx]   = excl;
        }
        __syncthreads();
        if (tid == 1023) carry_s = carry + sh[1023];
        __syncthreads();
    }
    if (tid == 0) g_rowptr[Gc] = carry_s;
}

__global__ void scatter_kernel(const int* __restrict__ erow,
                               const int* __restrict__ ecol,
                               const float* __restrict__ ev, int E) {
    int i = blockIdx.x * blockDim.x + threadIdx.x;
    if (i < E) {
        int r = erow[i];
        int p = atomicAdd(&g_fill[r], 1);
        g_ecol[p] = ecol[i];
        g_eval[p] = ev[i];
    }
}

// ---------------- build combined Wkq [j][32] --------------------------------
__global__ void build_wkq_kernel(const float* __restrict__ Wk,
                                 const float* __restrict__ Wq) {
    int i = blockIdx.x * blockDim.x + threadIdx.x;   // 2048
    if (i < Cc * KDc) {
        int j = i >> 4, d = i & 15;
        g_Wkq[j * 32 + d]      = Wk[i];
        g_Wkq[j * 32 + 16 + d] = Wq[i];
    }
}

// ---------------- weights: w[R] (+)= mean_d( (s@Wk)_d * (s@Wq)_d ) ----------
// Block = 32 rows (in smem). 8 warps; warp handles 4 rows; lane = combined
// k/q output dim (0-15 = k_d, 16-31 = q_d). Wkq loads are fully coalesced.
__global__ void weights2_kernel(const float* __restrict__ x, int sel, int accum) {
    const float* state = (sel == 0) ? x : (sel == 1 ? g_bufA : g_bufB);
    __shared__ __align__(16) float s[32][Cc];

    int tid = threadIdx.x;                    // 256
    size_t base = (size_t)blockIdx.x * 32 * Cc;
    const float4* gp = reinterpret_cast<const float4*>(state + base);
    float4* sp = reinterpret_cast<float4*>(&s[0][0]);
    #pragma unroll
    for (int i = 0; i < 4; i++) sp[tid + i * 256] = gp[tid + i * 256];
    __syncthreads();

    int w = tid >> 5, lane = tid & 31;
    const float* r0 = s[w * 4 + 0];
    const float* r1 = s[w * 4 + 1];
    const float* r2 = s[w * 4 + 2];
    const float* r3 = s[w * 4 + 3];

    float a0 = 0.f, a1 = 0.f, a2 = 0.f, a3 = 0.f;
    #pragma unroll 4
    for (int j = 0; j < Cc; j++) {
        float wkq = g_Wkq[j * 32 + lane];     // coalesced 128B
        a0 += r0[j] * wkq;
        a1 += r1[j] * wkq;
        a2 += r2[j] * wkq;
        a3 += r3[j] * wkq;
    }

    float p[4];
    p[0] = a0 * __shfl_xor_sync(0xffffffffu, a0, 16);
    p[1] = a1 * __shfl_xor_sync(0xffffffffu, a1, 16);
    p[2] = a2 * __shfl_xor_sync(0xffffffffu, a2, 16);
    p[3] = a3 * __shfl_xor_sync(0xffffffffu, a3, 16);
    #pragma unroll
    for (int r = 0; r < 4; r++) {
        #pragma unroll
        for (int o = 8; o; o >>= 1)
            p[r] += __shfl_xor_sync(0xffffffffu, p[r], o);
    }
    if (lane == 0) {
        int R = blockIdx.x * 32 + w * 4;
        #pragma unroll
        for (int r = 0; r < 4; r++) {
            float val = p[r] * (1.0f / KDc);
            g_weights[R + r] = accum ? (g_weights[R + r] + val) : val;
        }
    }
}

// ---------------- SPMM: dst[l,g,:] = 0.5 * sum_e val_e * src[l,col_e,:] ----
__global__ void spmm_kernel(const float* __restrict__ x, int iter) {
    const float* src = (iter == 0) ? x : g_bufA;
    float* dst       = (iter == 0) ? g_bufA : g_bufB;

    int g = blockIdx.x;
    int t = threadIdx.x;               // 128
    int l  = t >> 5;
    int c4 = (t & 31) * 4;

    int s = g_rowptr[g], e = g_rowptr[g + 1];
    __shared__ int   scol[128];
    __shared__ float sval[128];

    float4 acc = make_float4(0.f, 0.f, 0.f, 0.f);
    const float* srcb = src + (size_t)l * Gc * Cc + c4;

    for (int base = s; base < e; base += 128) {
        int n = min(128, e - base);
        if (t < n) {
            scol[t] = g_ecol[base + t];
            sval[t] = g_eval[base + t];
        }
        __syncthreads();
        #pragma unroll 8
        for (int i = 0; i < n; i++) {
            float v = sval[i];
            int  cc = scol[i];
            float4 sv = *reinterpret_cast<const float4*>(srcb + (size_t)cc * Cc);
            acc.x += v * sv.x; acc.y += v * sv.y;
            acc.z += v * sv.z; acc.w += v * sv.w;
        }
        __syncthreads();
    }
    float4 o = make_float4(acc.x * 0.5f, acc.y * 0.5f, acc.z * 0.5f, acc.w * 0.5f);
    *reinterpret_cast<float4*>(dst + ((size_t)l * Gc + g) * Cc + c4) = o;
}

// ---------------- final: values = (x+A+B)@Wv, v = values*w, LayerNorm -------
// Block = 32 rows (smem tile). Warp handles 4 rows; lane handles 4 cols.
// Wv accessed row-major, float4 per lane -> fully coalesced 512B per warp.
__global__ void final2_kernel(const float* __restrict__ x,
                              const float* __restrict__ Wv,
                              const float* __restrict__ gamma,
                              const float* __restrict__ beta,
                              float* __restrict__ out) {
    __shared__ __align__(16) float s[32][Cc];
    int tid = threadIdx.x;                    // 256
    size_t base = (size_t)blockIdx.x * 32 * Cc;

    const float4* xp = reinterpret_cast<const float4*>(x + base);
    const float4* ap = reinterpret_cast<const float4*>(g_bufA + base);
    const float4* bp = reinterpret_cast<const float4*>(g_bufB + base);
    float4* sp = reinterpret_cast<float4*>(&s[0][0]);
    #pragma unroll
    for (int i = 0; i < 4; i++) {
        float4 a = xp[tid + i * 256];
        float4 b = ap[tid + i * 256];
        float4 c = bp[tid + i * 256];
        sp[tid + i * 256] = make_float4(a.x + b.x + c.x, a.y + b.y + c.y,
                                        a.z + b.z + c.z, a.w + b.w + c.w);
    }
    __syncthreads();

    int w = tid >> 5, lane = tid & 31;
    const float* r0 = s[w * 4 + 0];
    const float* r1 = s[w * 4 + 1];
    const float* r2 = s[w * 4 + 2];
    const float* r3 = s[w * 4 + 3];

    // accumulators: per row, cols (4*lane, 4*lane+1) and (4*lane+2, 4*lane+3)
    unsigned long long accA[4] = {0ull, 0ull, 0ull, 0ull};
    unsigned long long accB[4] = {0ull, 0ull, 0ull, 0ull};
    const float4* wvp = reinterpret_cast<const float4*>(Wv) + lane;

    #pragma unroll 4
    for (int j = 0; j < Cc; j++) {
        float4 wv = wvp[j * 32];              // coalesced 512B per warp
        unsigned long long wlo = pack2(wv.x, wv.y);
        unsigned long long whi = pack2(wv.z, wv.w);
        unsigned long long s0 = pack2(r0[j], r0[j]);
        unsigned long long s1 = pack2(r1[j], r1[j]);
        unsigned long long s2 = pack2(r2[j], r2[j]);
        unsigned long long s3 = pack2(r3[j], r3[j]);
        fma2(accA[0], s0, wlo); fma2(accB[0], s0, whi);
        fma2(accA[1], s1, wlo); fma2(accB[1], s1, whi);
        fma2(accA[2], s2, wlo); fma2(accB[2], s2, whi);
        fma2(accA[3], s3, wlo); fma2(accB[3], s3, whi);
    }

    float4 g4 = reinterpret_cast<const float4*>(gamma)[lane];
    float4 b4 = reinterpret_cast<const float4*>(beta)[lane];
    int Rbase = blockIdx.x * 32 + w * 4;

    #pragma unroll
    for (int r = 0; r < 4; r++) {
        float wt = g_weights[Rbase + r];
        float v0, v1, v2, v3;
        unpack2(accA[r], v0, v1);
        unpack2(accB[r], v2, v3);
        v0 *= wt; v1 *= wt; v2 *= wt; v3 *= wt;

        float t = v0 + v1 + v2 + v3;
        #pragma unroll
        for (int o = 16; o; o >>= 1) t += __shfl_xor_sync(0xffffffffu, t, o);
        float mu = t * (1.0f / Cc);
        float d0 = v0 - mu, d1 = v1 - mu, d2 = v2 - mu, d3 = v3 - mu;
        t = d0 * d0 + d1 * d1 + d2 * d2 + d3 * d3;
        #pragma unroll
        for (int o = 16; o; o >>= 1) t += __shfl_xor_sync(0xffffffffu, t, o);
        float rstd = rsqrtf(t * (1.0f / Cc) + LN_EPS);

        float4 o4 = make_float4(d0 * rstd * g4.x + b4.x,
                                d1 * rstd * g4.y + b4.y,
                                d2 * rstd * g4.z + b4.z,
                                d3 * rstd * g4.w + b4.w);
        reinterpret_cast<float4*>(out)[(size_t)(Rbase + r) * 32 + lane] = o4;
    }
}

// ---------------- launch ----------------------------------------------------
extern "C" void kernel_launch(void* const* d_in, const int* in_sizes, int n_in,
                              void* d_out, int out_size) {
    const float* x     = (const float*)d_in[0];
    const int*   erow  = (const int*)  d_in[1];
    const int*   ecol  = (const int*)  d_in[2];
    const float* evals = (const float*)d_in[3];
    const float* Wk    = (const float*)d_in[4];
    const float* Wq    = (const float*)d_in[5];
    const float* Wv    = (const float*)d_in[6];
    const float* gamma = (const float*)d_in[7];
    const float* beta  = (const float*)d_in[8];
    float* out = (float*)d_out;
    int E = in_sizes[1];
    if (E > Ec) E = Ec;

    // CSR build
    zero_cnt_kernel<<<(Gc + 255) / 256, 256>>>();
    count_kernel<<<(E + 255) / 256, 256>>>(erow, E);
    scan_kernel<<<1, 1024>>>();
    scatter_kernel<<<(E + 255) / 256, 256>>>(erow, ecol, evals, E);

    // combined Wk|Wq
    build_wkq_kernel<<<8, 256>>>(Wk, Wq);

    const int WBLOCKS = NROWS / 32;   // 2500

    // weights from x; two SPMM iterations, each adding weight contribution
    weights2_kernel<<<WBLOCKS, 256>>>(x, 0, 0);
    spmm_kernel<<<Gc, 128>>>(x, 0);
    weights2_kernel<<<WBLOCKS, 256>>>(x, 1, 1);
    spmm_kernel<<<Gc, 128>>>(x, 1);
    weights2_kernel<<<WBLOCKS, 256>>>(x, 2, 1);

    // fused GEMM + scale + LayerNorm
    final2_kernel<<<WBLOCKS, 256>>>(x, Wv, gamma, beta, out);
}

// round 4
// speedup vs baseline: 9.3026x; 1.0845x over previous
#include <cuda_runtime.h>
#include <cstdint>

// Problem constants (match reference)
#define Lc 4
#define Gc 20000
#define Cc 128
#define Ec 320000
#define KDc 16
#define NROWS (Lc*Gc)          // 80000 state rows of length 128
#define LN_EPS 1e-5f

// ---------------- device scratch (static: no allocation APIs) --------------
__device__ float g_bufA[(size_t)Lc*Gc*Cc];   // xr1
__device__ float g_bufB[(size_t)Lc*Gc*Cc];   // xr2
__device__ float g_weights[NROWS];
__device__ int   g_rowptr[Gc+1];
__device__ int   g_cnt[Gc];
__device__ int   g_fill[Gc];
__device__ int   g_ecol[Ec];
__device__ float g_eval[Ec];
__device__ float g_Wkq[Cc*32];               // [j][0:16]=Wk[j][:], [j][16:32]=Wq[j][:]

// ---------------- packed fp32x2 FMA helpers --------------------------------
__device__ __forceinline__ void fma2(unsigned long long& acc,
                                     unsigned long long a,
                                     unsigned long long b) {
    asm("fma.rn.f32x2 %0, %1, %2, %3;" : "=l"(acc) : "l"(a), "l"(b), "l"(acc));
}
__device__ __forceinline__ unsigned long long pack2(float lo, float hi) {
    unsigned long long v;
    asm("mov.b64 %0, {%1,%2};" : "=l"(v) : "f"(lo), "f"(hi));
    return v;
}
__device__ __forceinline__ void unpack2(unsigned long long v, float& lo, float& hi) {
    asm("mov.b64 {%0,%1}, %2;" : "=f"(lo), "=f"(hi) : "l"(v));
}

// ---------------- setup: zero counters + build combined Wkq ----------------
__global__ void setup_kernel(const float* __restrict__ Wk,
                             const float* __restrict__ Wq) {
    int i = blockIdx.x * blockDim.x + threadIdx.x;
    if (i < Gc) g_cnt[i] = 0;
    if (i < Cc * KDc) {
        int j = i >> 4, d = i & 15;
        g_Wkq[j * 32 + d]      = Wk[i];
        g_Wkq[j * 32 + 16 + d] = Wq[i];
    }
}

// ---------------- CSR build -------------------------------------------------
__global__ void count_kernel(const int* __restrict__ erow, int E) {
    int i = (blockIdx.x * blockDim.x + threadIdx.x) * 4;
    if (i + 3 < E) {
        int4 r = *reinterpret_cast<const int4*>(erow + i);
        atomicAdd(&g_cnt[r.x], 1);
        atomicAdd(&g_cnt[r.y], 1);
        atomicAdd(&g_cnt[r.z], 1);
        atomicAdd(&g_cnt[r.w], 1);
    } else {
        for (int k = i; k < E; k++) atomicAdd(&g_cnt[erow[k]], 1);
    }
}

// shfl-based scan, 1024 threads, 20 passes of 1024
__global__ void scan_kernel() {
    __shared__ int wsum[32];
    __shared__ int carry_s, tot_s;
    int tid = threadIdx.x;
    int wid = tid >> 5, lane = tid & 31;
    if (tid == 0) carry_s = 0;
    __syncthreads();
    for (int base = 0; base < Gc; base += 1024) {
        int idx = base + tid;
        int v = (idx < Gc) ? g_cnt[idx] : 0;
        // warp inclusive scan
        int inc = v;
        #pragma unroll
        for (int o = 1; o < 32; o <<= 1) {
            int t = __shfl_up_sync(0xffffffffu, inc, o);
            if (lane >= o) inc += t;
        }
        if (lane == 31) wsum[wid] = inc;
        __syncthreads();
        if (wid == 0) {
            int s = wsum[lane];
            int p = s;
            #pragma unroll
            for (int o = 1; o < 32; o <<= 1) {
                int t = __shfl_up_sync(0xffffffffu, p, o);
                if (lane >= o) p += t;
            }
            wsum[lane] = p - s;          // exclusive warp prefix
            if (lane == 31) tot_s = p;   // block total
        }
        __syncthreads();
        if (idx < Gc) {
            int excl = carry_s + wsum[wid] + inc - v;
            g_rowptr[idx] = excl;
            g_fill[idx]   = excl;
        }
        __syncthreads();
        if (tid == 0) carry_s += tot_s;
        __syncthreads();
    }
    if (tid == 0) g_rowptr[Gc] = carry_s;
}

__global__ void scatter_kernel(const int* __restrict__ erow,
                               const int* __restrict__ ecol,
                               const float* __restrict__ ev, int E) {
    int i = (blockIdx.x * blockDim.x + threadIdx.x) * 4;
    if (i + 3 < E) {
        int4   r = *reinterpret_cast<const int4*>(erow + i);
        int4   c = *reinterpret_cast<const int4*>(ecol + i);
        float4 v = *reinterpret_cast<const float4*>(ev + i);
        int p;
        p = atomicAdd(&g_fill[r.x], 1); g_ecol[p] = c.x; g_eval[p] = v.x;
        p = atomicAdd(&g_fill[r.y], 1); g_ecol[p] = c.y; g_eval[p] = v.y;
        p = atomicAdd(&g_fill[r.z], 1); g_ecol[p] = c.z; g_eval[p] = v.z;
        p = atomicAdd(&g_fill[r.w], 1); g_ecol[p] = c.w; g_eval[p] = v.w;
    } else {
        for (int k = i; k < E; k++) {
            int p = atomicAdd(&g_fill[erow[k]], 1);
            g_ecol[p] = ecol[k];
            g_eval[p] = ev[k];
        }
    }
}

// ---------------- weights: w[R] (+)= mean_d( (s@Wk)_d * (s@Wq)_d ) ----------
// Block = 32 rows. Wkq staged in smem (16KB): traffic 16KB/block not /warp.
// 8 warps; warp handles 4 rows; lane = combined k/q output dim.
__global__ void weights3_kernel(const float* __restrict__ x, int sel, int accum) {
    const float* state = (sel == 0) ? x : (sel == 1 ? g_bufA : g_bufB);
    __shared__ __align__(16) float s[32][Cc];
    __shared__ __align__(16) float wkq[Cc * 32];

    int tid = threadIdx.x;                    // 256
    size_t base = (size_t)blockIdx.x * 32 * Cc;
    const float4* gp = reinterpret_cast<const float4*>(state + base);
    float4* sp = reinterpret_cast<float4*>(&s[0][0]);
    const float4* wg = reinterpret_cast<const float4*>(g_Wkq);
    float4* wsp = reinterpret_cast<float4*>(wkq);
    #pragma unroll
    for (int i = 0; i < 4; i++) {
        sp[tid + i * 256]  = gp[tid + i * 256];
        wsp[tid + i * 256] = wg[tid + i * 256];
    }
    __syncthreads();

    int w = tid >> 5, lane = tid & 31;
    const float* r0 = s[w * 4 + 0];
    const float* r1 = s[w * 4 + 1];
    const float* r2 = s[w * 4 + 2];
    const float* r3 = s[w * 4 + 3];

    float a0 = 0.f, a1 = 0.f, a2 = 0.f, a3 = 0.f;
    #pragma unroll 8
    for (int j4 = 0; j4 < Cc / 4; j4++) {
        float4 v0 = *reinterpret_cast<const float4*>(r0 + j4 * 4);
        float4 v1 = *reinterpret_cast<const float4*>(r1 + j4 * 4);
        float4 v2 = *reinterpret_cast<const float4*>(r2 + j4 * 4);
        float4 v3 = *reinterpret_cast<const float4*>(r3 + j4 * 4);
        float w0 = wkq[(j4 * 4 + 0) * 32 + lane];
        float w1 = wkq[(j4 * 4 + 1) * 32 + lane];
        float w2 = wkq[(j4 * 4 + 2) * 32 + lane];
        float w3 = wkq[(j4 * 4 + 3) * 32 + lane];
        a0 += v0.x * w0 + v0.y * w1 + v0.z * w2 + v0.w * w3;
        a1 += v1.x * w0 + v1.y * w1 + v1.z * w2 + v1.w * w3;
        a2 += v2.x * w0 + v2.y * w1 + v2.z * w2 + v2.w * w3;
        a3 += v3.x * w0 + v3.y * w1 + v3.z * w2 + v3.w * w3;
    }

    float p[4];
    p[0] = a0 * __shfl_xor_sync(0xffffffffu, a0, 16);
    p[1] = a1 * __shfl_xor_sync(0xffffffffu, a1, 16);
    p[2] = a2 * __shfl_xor_sync(0xffffffffu, a2, 16);
    p[3] = a3 * __shfl_xor_sync(0xffffffffu, a3, 16);
    #pragma unroll
    for (int r = 0; r < 4; r++) {
        #pragma unroll
        for (int o = 8; o; o >>= 1)
            p[r] += __shfl_xor_sync(0xffffffffu, p[r], o);
    }
    if (lane == 0) {
        int R = blockIdx.x * 32 + w * 4;
        #pragma unroll
        for (int r = 0; r < 4; r++) {
            float val = p[r] * (1.0f / KDc);
            g_weights[R + r] = accum ? (g_weights[R + r] + val) : val;
        }
    }
}

// ---------------- SPMM: dst[l,g,:] = 0.5 * sum_e val_e * src[l,col_e,:] ----
__global__ void spmm_kernel(const float* __restrict__ x, int iter) {
    const float* src = (iter == 0) ? x : g_bufA;
    float* dst       = (iter == 0) ? g_bufA : g_bufB;

    int g = blockIdx.x;
    int t = threadIdx.x;               // 128
    int l  = t >> 5;
    int c4 = (t & 31) * 4;

    int s = g_rowptr[g], e = g_rowptr[g + 1];
    __shared__ int   scol[128];
    __shared__ float sval[128];

    float4 acc = make_float4(0.f, 0.f, 0.f, 0.f);
    const float* srcb = src + (size_t)l * Gc * Cc + c4;

    for (int base = s; base < e; base += 128) {
        int n = min(128, e - base);
        if (t < n) {
            scol[t] = g_ecol[base + t];
            sval[t] = g_eval[base + t];
        }
        __syncthreads();
        #pragma unroll 8
        for (int i = 0; i < n; i++) {
            float v = sval[i];
            int  cc = scol[i];
            float4 sv = *reinterpret_cast<const float4*>(srcb + (size_t)cc * Cc);
            acc.x += v * sv.x; acc.y += v * sv.y;
            acc.z += v * sv.z; acc.w += v * sv.w;
        }
        __syncthreads();
    }
    float4 o = make_float4(acc.x * 0.5f, acc.y * 0.5f, acc.z * 0.5f, acc.w * 0.5f);
    *reinterpret_cast<float4*>(dst + ((size_t)l * Gc + g) * Cc + c4) = o;
}

// ---------------- final: values = (x+A+B)@Wv, v = values*w, LayerNorm -------
// Block = 32 rows. Wv (64KB) staged into dynamic smem once per block:
// L2 traffic for Wv drops 1.28GB -> 160MB. Warp = 4 rows, lane = 4 cols.
__global__ void final3_kernel(const float* __restrict__ x,
                              const float* __restrict__ Wv,
                              const float* __restrict__ gamma,
                              const float* __restrict__ beta,
                              float* __restrict__ out) {
    extern __shared__ __align__(16) float dyn[];
    float* wv_sm = dyn;                 // [128][128] = 16384 floats
    float (*s)[Cc] = reinterpret_cast<float(*)[Cc]>(dyn + Cc * Cc);  // [32][128]

    int tid = threadIdx.x;              // 256
    size_t base = (size_t)blockIdx.x * 32 * Cc;

    // stage Wv (64KB) coalesced
    const float4* wvg = reinterpret_cast<const float4*>(Wv);
    float4* wvs = reinterpret_cast<float4*>(wv_sm);
    #pragma unroll
    for (int i = 0; i < 16; i++) wvs[tid + i * 256] = wvg[tid + i * 256];

    // stage s = x + A + B
    const float4* xp = reinterpret_cast<const float4*>(x + base);
    const float4* ap = reinterpret_cast<const float4*>(g_bufA + base);
    const float4* bp = reinterpret_cast<const float4*>(g_bufB + base);
    float4* sp = reinterpret_cast<float4*>(&s[0][0]);
    #pragma unroll
    for (int i = 0; i < 4; i++) {
        float4 a = xp[tid + i * 256];
        float4 b = ap[tid + i * 256];
        float4 c = bp[tid + i * 256];
        sp[tid + i * 256] = make_float4(a.x + b.x + c.x, a.y + b.y + c.y,
                                        a.z + b.z + c.z, a.w + b.w + c.w);
    }
    __syncthreads();

    int w = tid >> 5, lane = tid & 31;
    const float* r0 = s[w * 4 + 0];
    const float* r1 = s[w * 4 + 1];
    const float* r2 = s[w * 4 + 2];
    const float* r3 = s[w * 4 + 3];

    unsigned long long accA[4] = {0ull, 0ull, 0ull, 0ull};
    unsigned long long accB[4] = {0ull, 0ull, 0ull, 0ull};

    #pragma unroll 4
    for (int j = 0; j < Cc; j++) {
        float4 wv = *reinterpret_cast<const float4*>(wv_sm + j * Cc + lane * 4);
        unsigned long long wlo = pack2(wv.x, wv.y);
        unsigned long long whi = pack2(wv.z, wv.w);
        unsigned long long s0 = pack2(r0[j], r0[j]);
        unsigned long long s1 = pack2(r1[j], r1[j]);
        unsigned long long s2 = pack2(r2[j], r2[j]);
        unsigned long long s3 = pack2(r3[j], r3[j]);
        fma2(accA[0], s0, wlo); fma2(accB[0], s0, whi);
        fma2(accA[1], s1, wlo); fma2(accB[1], s1, whi);
        fma2(accA[2], s2, wlo); fma2(accB[2], s2, whi);
        fma2(accA[3], s3, wlo); fma2(accB[3], s3, whi);
    }

    float4 g4 = reinterpret_cast<const float4*>(gamma)[lane];
    float4 b4 = reinterpret_cast<const float4*>(beta)[lane];
    int Rbase = blockIdx.x * 32 + w * 4;

    #pragma unroll
    for (int r = 0; r < 4; r++) {
        float wt = g_weights[Rbase + r];
        float v0, v1, v2, v3;
        unpack2(accA[r], v0, v1);
        unpack2(accB[r], v2, v3);
        v0 *= wt; v1 *= wt; v2 *= wt; v3 *= wt;

        float t = v0 + v1 + v2 + v3;
        #pragma unroll
        for (int o = 16; o; o >>= 1) t += __shfl_xor_sync(0xffffffffu, t, o);
        float mu = t * (1.0f / Cc);
        float d0 = v0 - mu, d1 = v1 - mu, d2 = v2 - mu, d3 = v3 - mu;
        t = d0 * d0 + d1 * d1 + d2 * d2 + d3 * d3;
        #pragma unroll
        for (int o = 16; o; o >>= 1) t += __shfl_xor_sync(0xffffffffu, t, o);
        float rstd = rsqrtf(t * (1.0f / Cc) + LN_EPS);

        float4 o4 = make_float4(d0 * rstd * g4.x + b4.x,
                                d1 * rstd * g4.y + b4.y,
                                d2 * rstd * g4.z + b4.z,
                                d3 * rstd * g4.w + b4.w);
        reinterpret_cast<float4*>(out)[(size_t)(Rbase + r) * 32 + lane] = o4;
    }
}

// ---------------- launch ----------------------------------------------------
extern "C" void kernel_launch(void* const* d_in, const int* in_sizes, int n_in,
                              void* d_out, int out_size) {
    const float* x     = (const float*)d_in[0];
    const int*   erow  = (const int*)  d_in[1];
    const int*   ecol  = (const int*)  d_in[2];
    const float* evals = (const float*)d_in[3];
    const float* Wk    = (const float*)d_in[4];
    const float* Wq    = (const float*)d_in[5];
    const float* Wv    = (const float*)d_in[6];
    const float* gamma = (const float*)d_in[7];
    const float* beta  = (const float*)d_in[8];
    float* out = (float*)d_out;
    int E = in_sizes[1];
    if (E > Ec) E = Ec;

    // CSR build + Wkq
    setup_kernel<<<(Gc + 255) / 256, 256>>>(Wk, Wq);
    int eblk = ((E + 3) / 4 + 255) / 256;
    count_kernel<<<eblk, 256>>>(erow, E);
    scan_kernel<<<1, 1024>>>();
    scatter_kernel<<<eblk, 256>>>(erow, ecol, evals, E);

    const int WBLOCKS = NROWS / 32;   // 2500

    weights3_kernel<<<WBLOCKS, 256>>>(x, 0, 0);
    spmm_kernel<<<Gc, 128>>>(x, 0);
    weights3_kernel<<<WBLOCKS, 256>>>(x, 1, 1);
    spmm_kernel<<<Gc, 128>>>(x, 1);
    weights3_kernel<<<WBLOCKS, 256>>>(x, 2, 1);

    // fused GEMM + scale + LayerNorm (Wv staged in 64KB dynamic smem)
    static const int FINAL_SMEM = (Cc * Cc + 32 * Cc) * sizeof(float); // 80KB
    cudaFuncSetAttribute(final3_kernel,
                         cudaFuncAttributeMaxDynamicSharedMemorySize, FINAL_SMEM);
    final3_kernel<<<WBLOCKS, 256, FINAL_SMEM>>>(x, Wv, gamma, beta, out);
}